// round 1
// baseline (speedup 1.0000x reference)
#include <cuda_runtime.h>
#include <cstdint>

// AdaptiveSparseVoxels: expand N parents -> 8N children.
// Output layout (float32): [8N x 32] row-major feature matrix, then 8N morton
// codes cast to float (concatenation of the reference's tuple outputs).
//
// Row layout (32 floats = 128B): px py pz size dens c0..c26
//
// Thread mapping: one float4 per thread. tid -> (row = tid>>3, j = tid&7).
// Each consecutive 8 lanes write one contiguous 128B line: fully coalesced.

__device__ __forceinline__ unsigned part1by2(unsigned n) {
    n &= 1023u;
    n = (n ^ (n << 16)) & 0xFF0000FFu;
    n = (n ^ (n << 8))  & 0x0300F00Fu;
    n = (n ^ (n << 4))  & 0x030C30C3u;
    n = (n ^ (n << 2))  & 0x09249249u;
    return n;
}

__device__ __forceinline__ int coord_of(float p, float fres, int resm1) {
    // reference: ((p - (-1)) / 2 * res).astype(int32) then clip(0, res-1)
    // /2 and *res are exact power-of-2 ops; only the add rounds.
    float norm = __fmul_rn(__fmul_rn(__fadd_rn(p, 1.0f), 0.5f), fres);
    int c = (int)norm;               // trunc toward zero, same as astype(int32)
    c = c < 0 ? 0 : (c > resm1 ? resm1 : c);
    return c;
}

__global__ void asv_expand_kernel(
    const float*  __restrict__ positions,   // [N,3]
    const float*  __restrict__ sizes,       // [N]
    const float*  __restrict__ densities,   // [N]
    const float*  __restrict__ colors,      // [N,27]
    const int*    __restrict__ level_p,     // [1]
    float*        __restrict__ out,         // [8N*32] + [8N] morton-as-float
    long long nrows)                        // 8N
{
    long long tid = (long long)blockIdx.x * blockDim.x + threadIdx.x;
    long long nq = nrows << 3;              // total float4 slots
    if (tid >= nq) return;

    const int       j   = (int)(tid & 7);
    const long long row = tid >> 3;
    const long long p   = row >> 3;
    const int       oct = (int)(row & 7);

    float4 v;

    if (j == 0) {
        // positions / size / morton path
        float s  = __ldg(&sizes[p]);
        float q  = 0.25f * s;               // exact (power-of-2 scale)
        float ox = (oct & 1) ? q : -q;
        float oy = (oct & 2) ? q : -q;
        float oz = (oct & 4) ? q : -q;
        float px = __fadd_rn(__ldg(&positions[p * 3 + 0]), ox);
        float py = __fadd_rn(__ldg(&positions[p * 3 + 1]), oy);
        float pz = __fadd_rn(__ldg(&positions[p * 3 + 2]), oz);

        v.x = px; v.y = py; v.z = pz; v.w = 0.5f * s;

        // morton
        int level = __ldg(level_p);
        int res   = 64 << level;
        float fres = (float)res;
        int resm1 = res - 1;
        unsigned cx = (unsigned)coord_of(px, fres, resm1);
        unsigned cy = (unsigned)coord_of(py, fres, resm1);
        unsigned cz = (unsigned)coord_of(pz, fres, resm1);
        unsigned code = (part1by2(cz) << 2) + (part1by2(cy) << 1) + part1by2(cx);
        // morton < 2^(3*log2(res)) <= 2^21 at level 1: exact in float32
        out[nrows * 32 + row] = (float)(int)code;
    } else if (j == 1) {
        const float* cb = colors + p * 27;
        v.x = __ldg(&densities[p]);
        v.y = __ldg(&cb[0]);
        v.z = __ldg(&cb[1]);
        v.w = __ldg(&cb[2]);
    } else {
        const float* cb = colors + p * 27;
        int k = 4 * j - 5;                  // j=2 -> c3..c6, ..., j=7 -> c23..c26
        v.x = __ldg(&cb[k + 0]);
        v.y = __ldg(&cb[k + 1]);
        v.z = __ldg(&cb[k + 2]);
        v.w = __ldg(&cb[k + 3]);
    }

    reinterpret_cast<float4*>(out)[tid] = v;
}

extern "C" void kernel_launch(void* const* d_in, const int* in_sizes, int n_in,
                              void* d_out, int out_size) {
    const float* positions = (const float*)d_in[0];
    const float* sizes     = (const float*)d_in[1];
    const float* densities = (const float*)d_in[2];
    const float* colors    = (const float*)d_in[3];
    const int*   level     = (const int*)d_in[4];

    long long N     = in_sizes[0] / 3;
    long long nrows = N * 8;
    long long nq    = nrows * 8;

    float* out = (float*)d_out;

    const int threads = 256;
    long long blocks = (nq + threads - 1) / threads;
    asv_expand_kernel<<<(unsigned)blocks, threads>>>(
        positions, sizes, densities, colors, level, out, nrows);
}

// round 2
// speedup vs baseline: 1.0529x; 1.0529x over previous
#include <cuda_runtime.h>
#include <cstdint>

// AdaptiveSparseVoxels: expand N parents -> 8N children.
// Output (float32): [8N x 32] row-major features, then 8N morton-as-float.
// Row layout: px py pz size dens c0..c26  (32 floats = 128B)
//
// Block = 256 threads = 4 parents (64 output-float4s per parent).
// Phase 1: stage each parent's 32-float record in smem (every input float
//          loaded exactly once per block). Record layout:
//          [dens, c0..c26, px, py, pz, s]  -> word index 0..31
// Phase 2: thread q handles output float4 (row = q>>3, j = q&7):
//          j>=1 : LDS.128 of words 4(j-1)..4(j-1)+3   (dens+colors tail)
//          j==0 : LDS.128 of words 28..31 (px,py,pz,s), compute child
//                 pos/size + morton (predicated, 4 lanes/warp).
// All lanes of a warp read one parent's 128B smem row: conflict-free.

#define PPB 4              // parents per block
#define TPB 256            // = PPB * 64

__device__ __forceinline__ unsigned part1by2(unsigned n) {
    n &= 1023u;
    n = (n ^ (n << 16)) & 0xFF0000FFu;
    n = (n ^ (n << 8))  & 0x0300F00Fu;
    n = (n ^ (n << 4))  & 0x030C30C3u;
    n = (n ^ (n << 2))  & 0x09249249u;
    return n;
}

__device__ __forceinline__ unsigned coord_of(float p, float fres, int resm1) {
    // reference: ((p + 1) / 2 * res).astype(int32) then clip(0, res-1)
    float norm = __fmul_rn(__fmul_rn(__fadd_rn(p, 1.0f), 0.5f), fres);
    int c = (int)norm;                 // trunc toward zero == astype(int32)
    c = c < 0 ? 0 : (c > resm1 ? resm1 : c);
    return (unsigned)c;
}

__global__ void __launch_bounds__(TPB)
asv_expand_kernel(
    const float* __restrict__ positions,   // [N,3]
    const float* __restrict__ sizes,       // [N]
    const float* __restrict__ densities,   // [N]
    const float* __restrict__ colors,      // [N,27]
    const int*   __restrict__ level_p,     // [1]
    float*       __restrict__ out,         // [8N*32] + [8N] morton-as-float
    unsigned N, unsigned nrows)            // nrows = 8N
{
    __shared__ float sm[PPB][32];

    const unsigned tid   = threadIdx.x;
    const unsigned pbase = blockIdx.x * PPB;

    // ---- Phase 1: stage PPB*32 = 128 floats, one per thread (tid < 128) ----
    if (tid < PPB * 32) {
        unsigned pl   = tid >> 5;          // parent local 0..3
        unsigned word = tid & 31;          // 0..31
        unsigned p    = pbase + pl;
        float v = 0.0f;
        if (p < N) {
            if (word == 0)        v = densities[p];
            else if (word <= 27)  v = colors[p * 27u + (word - 1u)];
            else if (word <= 30)  v = positions[p * 3u + (word - 28u)];
            else                  v = sizes[p];
        }
        sm[pl][word] = v;
    }
    __syncthreads();

    // ---- Phase 2: one float4 output per thread ----
    const unsigned q   = blockIdx.x * TPB + tid;   // global float4 index
    const unsigned row = q >> 3;                   // child row
    if (row >= nrows) return;

    const unsigned j   = q & 7u;                   // float4 slot within row
    const unsigned pl  = tid >> 6;                 // parent local (64 thr/parent)
    const unsigned oct = (row & 7u);

    float4 v;
    if (j == 0) {
        // words 28..31 = px,py,pz,s
        float4 ps = *reinterpret_cast<const float4*>(&sm[pl][28]);
        float s = ps.w;
        float qd = 0.25f * s;                      // exact
        float ox = (oct & 1u) ? qd : -qd;
        float oy = (oct & 2u) ? qd : -qd;
        float oz = (oct & 4u) ? qd : -qd;
        float px = __fadd_rn(ps.x, ox);
        float py = __fadd_rn(ps.y, oy);
        float pz = __fadd_rn(ps.z, oz);
        v.x = px; v.y = py; v.z = pz; v.w = 0.5f * s;

        int res = 64 << __ldg(level_p);
        float fres = (float)res;
        int resm1 = res - 1;
        unsigned code = (part1by2(coord_of(pz, fres, resm1)) << 2)
                      + (part1by2(coord_of(py, fres, resm1)) << 1)
                      +  part1by2(coord_of(px, fres, resm1));
        out[nrows * 32u + row] = (float)(int)code;  // exact: code < 2^21 typ.
    } else {
        // words 4(j-1)..4(j-1)+3 = dens,c0..c26 tail
        v = *reinterpret_cast<const float4*>(&sm[pl][(j - 1u) << 2]);
    }

    reinterpret_cast<float4*>(out)[q] = v;
}

extern "C" void kernel_launch(void* const* d_in, const int* in_sizes, int n_in,
                              void* d_out, int out_size) {
    const float* positions = (const float*)d_in[0];
    const float* sizes     = (const float*)d_in[1];
    const float* densities = (const float*)d_in[2];
    const float* colors    = (const float*)d_in[3];
    const int*   level     = (const int*)d_in[4];

    unsigned N     = (unsigned)(in_sizes[0] / 3);
    unsigned nrows = N * 8u;

    unsigned blocks = (N + PPB - 1) / PPB;
    asv_expand_kernel<<<blocks, TPB>>>(
        positions, sizes, densities, colors, level,
        (float*)d_out, N, nrows);
}

// round 3
// speedup vs baseline: 1.8885x; 1.7936x over previous
#include <cuda_runtime.h>
#include <cstdint>

// AdaptiveSparseVoxels: expand N parents -> 8N children.
// Output (float32): [8N x 32] row-major features, then 8N morton-as-float.
// Row layout: px py pz size dens c0..c26 (32 floats = 128B)
//
// Block = 256 threads = 32 parents = 256 child rows, 2 passes of 128 rows.
// A thread-pair (lanes 2l, 2l+1) owns one row; even lane writes the row's
// bytes [32k,32k+16), odd lane [32k+16,32k+32) for k=0..3 -> every STG.128
// warp op writes 16 FULL 32B sectors. Even lane also computes/stores morton.
//
// Parent records staged in smem, padded to stride 40 floats so the 4
// distinct LDS.128 addresses per warp hit disjoint bank groups.

#define P_PER_BLK 32
#define TPB 256
#define REC_STRIDE 40   // floats; 160B, 16B-aligned, conflict-free padding

__device__ __forceinline__ unsigned part1by2(unsigned n) {
    n &= 1023u;
    n = (n ^ (n << 16)) & 0xFF0000FFu;
    n = (n ^ (n << 8))  & 0x0300F00Fu;
    n = (n ^ (n << 4))  & 0x030C30C3u;
    n = (n ^ (n << 2))  & 0x09249249u;
    return n;
}

__device__ __forceinline__ unsigned coord_of(float p, float fres, int resm1) {
    // reference: ((p + 1) / 2 * res).astype(int32) then clip(0, res-1)
    float norm = __fmul_rn(__fmul_rn(__fadd_rn(p, 1.0f), 0.5f), fres);
    int c = (int)norm;                 // trunc toward zero == astype(int32)
    c = c < 0 ? 0 : (c > resm1 ? resm1 : c);
    return (unsigned)c;
}

__global__ void __launch_bounds__(TPB)
asv_expand_kernel(
    const float* __restrict__ positions,   // [N,3]
    const float* __restrict__ sizes,       // [N]
    const float* __restrict__ densities,   // [N]
    const float* __restrict__ colors,      // [N,27]
    const int*   __restrict__ level_p,     // [1]
    float*       __restrict__ out,         // [8N*32] + [8N] morton-as-float
    unsigned N, unsigned nrows)            // nrows = 8N
{
    __shared__ __align__(16) float sm[P_PER_BLK * REC_STRIDE];

    const unsigned tid   = threadIdx.x;
    const unsigned pbase = blockIdx.x * P_PER_BLK;

    // ---- Stage 32 parent records: [px,py,pz,s,dens,c0..c26] @ stride 40 ----
    #pragma unroll
    for (unsigned i = tid; i < P_PER_BLK * 27u; i += TPB) {
        unsigned p = i / 27u, c = i - p * 27u;
        if (pbase + p < N)
            sm[p * REC_STRIDE + 5u + c] = colors[(pbase + p) * 27u + c];
    }
    if (tid < P_PER_BLK * 3u) {
        unsigned p = tid / 3u, c = tid - p * 3u;
        if (pbase + p < N)
            sm[p * REC_STRIDE + c] = positions[(pbase + p) * 3u + c];
    }
    if (tid < P_PER_BLK) {
        if (pbase + tid < N) {
            sm[tid * REC_STRIDE + 3u] = sizes[pbase + tid];
            sm[tid * REC_STRIDE + 4u] = densities[pbase + tid];
        }
    }
    __syncthreads();

    const int   res   = 64 << __ldg(level_p);
    const float fres  = (float)res;
    const int   resm1 = res - 1;

    const unsigned half    = tid & 1u;   // 0: low 16 floats, 1: high 16
    const unsigned pairIdx = tid >> 1;   // row within pass (0..127)

    #pragma unroll
    for (int pass = 0; pass < 2; pass++) {
        const unsigned row_local = (unsigned)pass * 128u + pairIdx; // 0..255
        const unsigned pl        = row_local >> 3;                  // 0..31
        const unsigned oct       = row_local & 7u;
        const unsigned p         = pbase + pl;
        if (p >= N) continue;
        const unsigned row = pbase * 8u + row_local;

        const float* rec = &sm[pl * REC_STRIDE];

        // child position (all lanes; cheap, avoids divergence)
        float s  = rec[3];
        float qd = 0.25f * s;                         // exact
        float px = __fadd_rn(rec[0], (oct & 1u) ? qd : -qd);
        float py = __fadd_rn(rec[1], (oct & 2u) ? qd : -qd);
        float pz = __fadd_rn(rec[2], (oct & 4u) ? qd : -qd);

        if (half == 0u) {
            unsigned code = (part1by2(coord_of(pz, fres, resm1)) << 2)
                          + (part1by2(coord_of(py, fres, resm1)) << 1)
                          +  part1by2(coord_of(px, fres, resm1));
            out[nrows * 32u + row] = (float)(int)code; // exact: code < 2^21
        }

        float* orow = out + (size_t)row * 32u + half * 4u;
        #pragma unroll
        for (int k = 0; k < 4; k++) {
            float4 v = *reinterpret_cast<const float4*>(rec + 8 * k + 4 * half);
            if (k == 0 && half == 0u) {               // branchless selects
                v.x = px; v.y = py; v.z = pz; v.w = 0.5f * s;
            }
            *reinterpret_cast<float4*>(orow + 8 * k) = v;
        }
    }
}

extern "C" void kernel_launch(void* const* d_in, const int* in_sizes, int n_in,
                              void* d_out, int out_size) {
    const float* positions = (const float*)d_in[0];
    const float* sizes     = (const float*)d_in[1];
    const float* densities = (const float*)d_in[2];
    const float* colors    = (const float*)d_in[3];
    const int*   level     = (const int*)d_in[4];

    unsigned N     = (unsigned)(in_sizes[0] / 3);
    unsigned nrows = N * 8u;

    unsigned blocks = (N + P_PER_BLK - 1) / P_PER_BLK;
    asv_expand_kernel<<<blocks, TPB>>>(
        positions, sizes, densities, colors, level,
        (float*)d_out, N, nrows);
}